// round 15
// baseline (speedup 1.0000x reference)
#include <cuda_runtime.h>
#include <math.h>
#include <stdint.h>

// ---------------------------------------------------------------------------
// Problem constants
// ---------------------------------------------------------------------------
#define Bz  32
#define Sz  512
#define Dz  512
#define Hz  8
#define HDz 64
#define FFz 2048
#define Lz  6
#define INz 32
#define OUTz 3
#define BS  (Bz * Sz)

// ---------------------------------------------------------------------------
// Scratch buffers
// ---------------------------------------------------------------------------
__device__ float g_h[BS * Dz];           // residual stream (full fp32)
__device__ float g_hr[BS * Dz];          // tf32-rounded copy (GEMM A input)
__device__ float g_qkv[BS * 3 * Dz];     // tf32-rounded by qkv epilogue
__device__ float g_attno[BS * Dz];       // tf32-rounded by attention epilogue
__device__ float g_ff[BS * FFz];         // tf32-rounded by ff1 epilogue
__device__ float g_res[BS * Dz];         // full fp32 (residual branch)

// Transposed + tf32-rounded weights: Wt[n][k]
#define WT_QKV 0
#define WT_OUT (Lz * Dz * 3 * Dz)
#define WT_FF1 (WT_OUT + Lz * Dz * Dz)
#define WT_FF2 (WT_FF1 + Lz * Dz * FFz)
#define WT_TOTAL (WT_FF2 + Lz * FFz * Dz)
__device__ float g_wt[WT_TOTAL];

// ---------------------------------------------------------------------------
// Helpers
// ---------------------------------------------------------------------------
__device__ __forceinline__ float gelu_exact(float x) {
    return 0.5f * x * (1.0f + erff(x * 0.70710678118654752f));
}

__device__ __forceinline__ uint32_t f2tf32(float x) {
    uint32_t u;
    asm("cvt.rna.tf32.f32 %0, %1;" : "=r"(u) : "f"(x));
    return u;
}
__device__ __forceinline__ float roundtf(float x) {
    return __uint_as_float(f2tf32(x));
}

__device__ __forceinline__ void cp_async16(void* smem_dst, const void* gmem_src) {
    uint32_t s = (uint32_t)__cvta_generic_to_shared(smem_dst);
    asm volatile("cp.async.ca.shared.global [%0], [%1], 16;" :: "r"(s), "l"(gmem_src));
}
#define CP_COMMIT()  asm volatile("cp.async.commit_group;")
#define CP_WAIT1()   asm volatile("cp.async.wait_group 1;")
#define CP_WAIT0()   asm volatile("cp.async.wait_group 0;")

__device__ __forceinline__ void mma_tf32(float* c, const uint32_t* a, const uint32_t* b) {
    asm volatile(
        "mma.sync.aligned.m16n8k8.row.col.f32.tf32.tf32.f32 "
        "{%0,%1,%2,%3},{%4,%5,%6,%7},{%8,%9},{%0,%1,%2,%3};"
        : "+f"(c[0]), "+f"(c[1]), "+f"(c[2]), "+f"(c[3])
        : "r"(a[0]), "r"(a[1]), "r"(a[2]), "r"(a[3]), "r"(b[0]), "r"(b[1]));
}

__device__ __forceinline__ void ldsm_x4(uint32_t* r, const float* p) {
    uint32_t a = (uint32_t)__cvta_generic_to_shared(p);
    asm volatile("ldmatrix.sync.aligned.m8n8.x4.shared.b16 {%0,%1,%2,%3}, [%4];"
        : "=r"(r[0]), "=r"(r[1]), "=r"(r[2]), "=r"(r[3]) : "r"(a));
}

__device__ __forceinline__ float block_reduce_sum_256(float v, float* red) {
    int tid = threadIdx.x;
    red[tid] = v;
    __syncthreads();
    #pragma unroll
    for (int s = 128; s > 0; s >>= 1) {
        if (tid < s) red[tid] += red[tid + s];
        __syncthreads();
    }
    float r = red[0];
    __syncthreads();
    return r;
}

// ---------------------------------------------------------------------------
// Weight transpose + tf32 round: dst[l][n][k] = tf32(src[l][k][n])
// ---------------------------------------------------------------------------
__global__ void transpose_round(const float* __restrict__ src,
                                float* __restrict__ dst, int K, int N) {
    __shared__ float t[32][33];
    int l = blockIdx.z;
    src += (size_t)l * K * N;
    dst += (size_t)l * K * N;
    int n0 = blockIdx.x * 32;
    int k0 = blockIdx.y * 32;
    int tx = threadIdx.x, ty = threadIdx.y;
    #pragma unroll
    for (int i = 0; i < 32; i += 8)
        t[ty + i][tx] = src[(size_t)(k0 + ty + i) * N + n0 + tx];
    __syncthreads();
    #pragma unroll
    for (int i = 0; i < 32; i += 8)
        dst[(size_t)(n0 + ty + i) * K + k0 + tx] = roundtf(t[tx][ty + i]);
}

// ---------------------------------------------------------------------------
// Embed (writes g_h fp32 + g_hr tf32)
// ---------------------------------------------------------------------------
__global__ void embed_kernel(const float* __restrict__ x,
                             const float* __restrict__ w_in,
                             const float* __restrict__ b_in,
                             const float* __restrict__ g_in,
                             const float* __restrict__ be_in) {
    int t = blockIdx.x;
    int tid = threadIdx.x;
    __shared__ float xrow[INz];
    __shared__ float vals[Dz];
    __shared__ float red[256];

    if (tid < INz) xrow[tid] = x[t * INz + tid];
    __syncthreads();

    #pragma unroll
    for (int p = 0; p < 2; p++) {
        int c = tid + p * 256;
        float acc = b_in[c];
        #pragma unroll
        for (int k = 0; k < INz; k++) acc += xrow[k] * w_in[k * Dz + c];
        vals[c] = acc;
    }
    __syncthreads();

    float v0 = vals[tid], v1 = vals[tid + 256];
    float mu = block_reduce_sum_256(v0 + v1, red) * (1.0f / Dz);
    float d0 = v0 - mu, d1 = v1 - mu;
    float var = block_reduce_sum_256(d0 * d0 + d1 * d1, red) * (1.0f / Dz);
    float inv = rsqrtf(var + 1e-5f);

    int s = t % Sz;
    float pos = (float)s;
    const float kLog = 9.210340371976184f / (float)Dz;

    #pragma unroll
    for (int p = 0; p < 2; p++) {
        int c = tid + p * 256;
        float d = (p == 0 ? d0 : d1);
        float y = d * inv * g_in[c] + be_in[c];
        y = gelu_exact(y);
        int i2 = c & ~1;
        float div = __expf(-(float)i2 * kLog);
        float ang = pos * div;
        y += (c & 1) ? cosf(ang) : sinf(ang);
        g_h[t * Dz + c] = y;
        g_hr[t * Dz + c] = roundtf(y);
    }
}

// ---------------------------------------------------------------------------
// TF32 GEMM v8: 128x128 block tile, 256 threads / 8 warps (warp 64x32),
// TBK=16, 3-stage cp.async, 1 sync/k-iter, A/B via ldmatrix.x4, zero cvt.
// ~110 regs/thread -> 2 CTAs/SM = 16 warps/SM (vs 8 at the 4-warp shape).
// ACT: bit0 = gelu, bit1 = round output to tf32.
// ---------------------------------------------------------------------------
#define TBM 128
#define TBN 128
#define TBK 16
#define AST 20
#define GSTG 3
#define GEMM_SMEM ((GSTG * 2 * TBM * AST) * 4)   // 61440 B

template <int ACT>
__global__ __launch_bounds__(256)
void sgemm_tc(const float* __restrict__ A,
              const float* __restrict__ Wt,
              const float* __restrict__ bias,
              float* __restrict__ C,
              int M, int N, int K,
              int rowStride, int rowOff, int colOff) {
    extern __shared__ float gsm[];
    float* Asm = gsm;
    float* Bsm = gsm + GSTG * TBM * AST;

    int tid = threadIdx.x;
    int lane = tid & 31;
    int wid = tid >> 5;
    int wm = wid >> 2;          // 0..1 -> 64 rows
    int wn = wid & 3;           // 0..3 -> 32 cols
    int qk = lane & 3;
    int qr = lane >> 2;

    int rowBase = (blockIdx.y * rowStride + rowOff) * TBM;
    int colBase = blockIdx.x * TBN + colOff;

    int lr8 = lane & 7;
    int aoff = (lr8 + ((lane >> 3) & 1) * 8) * AST + ((lane >> 4) << 2);
    int bi = lane >> 3;
    int boff = (((bi >> 1) << 3) + lr8) * AST + ((bi & 1) << 2);

    float acc[4][4][4];
    #pragma unroll
    for (int i = 0; i < 4; i++)
        #pragma unroll
        for (int j = 0; j < 4; j++)
            #pragma unroll
            for (int c = 0; c < 4; c++) acc[i][j][c] = 0.f;

    int nk = K / TBK;

    auto stage = [&](int buf, int k0) {
        float* Ab = Asm + buf * TBM * AST;
        float* Bb = Bsm + buf * TBM * AST;
        #pragma unroll
        for (int p = 0; p < 2; p++) {
            int c = tid + p * 256;
            int row = c >> 2;
            int kc = (c & 3) << 2;
            cp_async16(&Ab[row * AST + kc],
                       A + (size_t)(rowBase + row) * K + k0 + kc);
            cp_async16(&Bb[row * AST + kc],
                       Wt + (size_t)(colBase + row) * K + k0 + kc);
        }
    };

    stage(0, 0);
    CP_COMMIT();
    stage(1, TBK);
    CP_COMMIT();

    for (int kt = 0; kt < nk; kt++) {
        CP_WAIT1();
        __syncthreads();
        if (kt + 2 < nk) {
            stage((kt + 2) % GSTG, (kt + 2) * TBK);
            CP_COMMIT();
        } else {
            CP_COMMIT();
        }

        const float* Ab = Asm + (kt % GSTG) * TBM * AST;
        const float* Bb = Bsm + (kt % GSTG) * TBM * AST;

        #pragma unroll
        for (int ks = 0; ks < TBK; ks += 8) {
            uint32_t af[4][4], bfr[2][4];
            #pragma unroll
            for (int mt = 0; mt < 4; mt++)
                ldsm_x4(af[mt], Ab + (wm * 64 + mt * 16) * AST + ks + aoff);
            #pragma unroll
            for (int p = 0; p < 2; p++)
                ldsm_x4(bfr[p], Bb + (wn * 32 + p * 16) * AST + ks + boff);

            #pragma unroll
            for (int mt = 0; mt < 4; mt++)
                #pragma unroll
                for (int nt = 0; nt < 4; nt++)
                    mma_tf32(acc[mt][nt], af[mt], &bfr[nt >> 1][(nt & 1) << 1]);
        }
    }

    #pragma unroll
    for (int mt = 0; mt < 4; mt++) {
        int row0 = rowBase + wm * 64 + mt * 16 + qr;
        #pragma unroll
        for (int nt = 0; nt < 4; nt++) {
            int col0 = colBase + wn * 32 + nt * 8 + 2 * qk;
            float bia0 = bias[col0], bia1 = bias[col0 + 1];
            float v0 = acc[mt][nt][0] + bia0;
            float v1 = acc[mt][nt][1] + bia1;
            float v2 = acc[mt][nt][2] + bia0;
            float v3 = acc[mt][nt][3] + bia1;
            if (ACT & 1) {
                v0 = gelu_exact(v0); v1 = gelu_exact(v1);
                v2 = gelu_exact(v2); v3 = gelu_exact(v3);
            }
            if (ACT & 2) {
                v0 = roundtf(v0); v1 = roundtf(v1);
                v2 = roundtf(v2); v3 = roundtf(v3);
            }
            *(float2*)&C[(size_t)row0 * N + col0] = make_float2(v0, v1);
            *(float2*)&C[(size_t)(row0 + 8) * N + col0] = make_float2(v2, v3);
        }
    }
}

// ---------------------------------------------------------------------------
// Tensor-core flash attention (unchanged)
// ---------------------------------------------------------------------------
#define QST 68
#define KST 68
#define VST 72
#define ATTN_SMEM ((64 * QST + 64 * KST + 64 * VST) * 4)

__global__ __launch_bounds__(128, 4)
void attn_flash_tc(int itOff) {
    extern __shared__ float sm[];
    float* Qs = sm;
    float* Ks = sm + 64 * QST;
    float* Vs = sm + 64 * QST + 64 * KST;

    int itile = blockIdx.x + itOff;
    int bh = blockIdx.y;
    int b = bh / Hz;
    int h = bh % Hz;
    int tid = threadIdx.x;
    int lane = tid & 31;
    int wid = tid >> 5;
    int qk = lane & 3;
    int qr = lane >> 2;
    int rbase = wid * 16;
    int i0 = itile * 64;
    size_t tokBase = (size_t)b * Sz;

    {
        const float* qb = g_qkv + (tokBase + i0) * (3 * Dz) + h * HDz;
        #pragma unroll
        for (int it = 0; it < 8; it++) {
            int idx = tid + it * 128;
            int j = idx >> 4;
            int dq = (idx & 15) << 2;
            cp_async16(&Qs[j * QST + dq], qb + (size_t)j * (3 * Dz) + dq);
        }
        CP_COMMIT();
    }

    float m0 = -1e30f, m1 = -1e30f, l0 = 0.f, l1 = 0.f;
    float o[8][4];
    #pragma unroll
    for (int dt = 0; dt < 8; dt++)
        #pragma unroll
        for (int c = 0; c < 4; c++) o[dt][c] = 0.f;

    for (int jt = 0; jt <= itile; jt++) {
        __syncthreads();
        {
            int j0 = jt * 64;
            const float* base0 = g_qkv + (tokBase + j0) * (3 * Dz) + h * HDz;
            #pragma unroll
            for (int it = 0; it < 8; it++) {
                int idx = tid + it * 128;
                int j = idx >> 4;
                int dq = (idx & 15) << 2;
                const float* base = base0 + (size_t)j * (3 * Dz) + dq;
                cp_async16(&Ks[j * KST + dq], base + Dz);
                cp_async16(&Vs[j * VST + dq], base + 2 * Dz);
            }
        }
        CP_COMMIT();
        CP_WAIT0();
        __syncthreads();

        float s[8][4];
        #pragma unroll
        for (int nt = 0; nt < 8; nt++)
            #pragma unroll
            for (int c = 0; c < 4; c++) s[nt][c] = 0.f;

        #pragma unroll
        for (int ks = 0; ks < 8; ks++) {
            int d0 = ks * 8 + qk;
            uint32_t af[4];
            int r0 = rbase + qr;
            af[0] = __float_as_uint(Qs[r0 * QST + d0]);
            af[1] = __float_as_uint(Qs[(r0 + 8) * QST + d0]);
            af[2] = __float_as_uint(Qs[r0 * QST + d0 + 4]);
            af[3] = __float_as_uint(Qs[(r0 + 8) * QST + d0 + 4]);
            #pragma unroll
            for (int nt = 0; nt < 8; nt++) {
                uint32_t bf[2];
                int jrow = nt * 8 + qr;
                bf[0] = __float_as_uint(Ks[jrow * KST + d0]);
                bf[1] = __float_as_uint(Ks[jrow * KST + d0 + 4]);
                mma_tf32(s[nt], af, bf);
            }
        }

        if (jt == itile) {
            int r0 = rbase + qr;
            #pragma unroll
            for (int nt = 0; nt < 8; nt++) {
                int j = nt * 8 + 2 * qk;
                s[nt][0] = (j > r0)         ? -1e30f : s[nt][0] * 0.125f;
                s[nt][1] = (j + 1 > r0)     ? -1e30f : s[nt][1] * 0.125f;
                s[nt][2] = (j > r0 + 8)     ? -1e30f : s[nt][2] * 0.125f;
                s[nt][3] = (j + 1 > r0 + 8) ? -1e30f : s[nt][3] * 0.125f;
            }
        } else {
            #pragma unroll
            for (int nt = 0; nt < 8; nt++) {
                s[nt][0] *= 0.125f; s[nt][1] *= 0.125f;
                s[nt][2] *= 0.125f; s[nt][3] *= 0.125f;
            }
        }

        float mx0 = -1e30f, mx1 = -1e30f;
        #pragma unroll
        for (int nt = 0; nt < 8; nt++) {
            mx0 = fmaxf(mx0, fmaxf(s[nt][0], s[nt][1]));
            mx1 = fmaxf(mx1, fmaxf(s[nt][2], s[nt][3]));
        }
        mx0 = fmaxf(mx0, __shfl_xor_sync(0xffffffffu, mx0, 1));
        mx0 = fmaxf(mx0, __shfl_xor_sync(0xffffffffu, mx0, 2));
        mx1 = fmaxf(mx1, __shfl_xor_sync(0xffffffffu, mx1, 1));
        mx1 = fmaxf(mx1, __shfl_xor_sync(0xffffffffu, mx1, 2));

        float nm0 = fmaxf(m0, mx0);
        float nm1 = fmaxf(m1, mx1);
        float e0 = __expf(m0 - nm0);
        float e1 = __expf(m1 - nm1);

        float rs0 = 0.f, rs1 = 0.f;
        #pragma unroll
        for (int nt = 0; nt < 8; nt++) {
            s[nt][0] = __expf(s[nt][0] - nm0);
            s[nt][1] = __expf(s[nt][1] - nm0);
            s[nt][2] = __expf(s[nt][2] - nm1);
            s[nt][3] = __expf(s[nt][3] - nm1);
            rs0 += s[nt][0] + s[nt][1];
            rs1 += s[nt][2] + s[nt][3];
        }
        rs0 += __shfl_xor_sync(0xffffffffu, rs0, 1);
        rs0 += __shfl_xor_sync(0xffffffffu, rs0, 2);
        rs1 += __shfl_xor_sync(0xffffffffu, rs1, 1);
        rs1 += __shfl_xor_sync(0xffffffffu, rs1, 2);

        l0 = l0 * e0 + rs0;
        l1 = l1 * e1 + rs1;
        m0 = nm0;
        m1 = nm1;
        #pragma unroll
        for (int dt = 0; dt < 8; dt++) {
            o[dt][0] *= e0; o[dt][1] *= e0;
            o[dt][2] *= e1; o[dt][3] *= e1;
        }

        int srcA = (lane & ~3) | (qk >> 1);
        int srcB = srcA + 2;
        bool odd = (qk & 1) != 0;
        #pragma unroll
        for (int nt = 0; nt < 8; nt++) {
            uint32_t p0 = f2tf32(s[nt][0]);
            uint32_t p1 = f2tf32(s[nt][1]);
            uint32_t p2 = f2tf32(s[nt][2]);
            uint32_t p3 = f2tf32(s[nt][3]);
            uint32_t af[4];
            uint32_t x, y;
            x = __shfl_sync(0xffffffffu, p0, srcA);
            y = __shfl_sync(0xffffffffu, p1, srcA);
            af[0] = odd ? y : x;
            x = __shfl_sync(0xffffffffu, p2, srcA);
            y = __shfl_sync(0xffffffffu, p3, srcA);
            af[1] = odd ? y : x;
            x = __shfl_sync(0xffffffffu, p0, srcB);
            y = __shfl_sync(0xffffffffu, p1, srcB);
            af[2] = odd ? y : x;
            x = __shfl_sync(0xffffffffu, p2, srcB);
            y = __shfl_sync(0xffffffffu, p3, srcB);
            af[3] = odd ? y : x;

            int jj = nt * 8 + qk;
            #pragma unroll
            for (int dt = 0; dt < 8; dt++) {
                uint32_t bf[2];
                int dn = dt * 8 + qr;
                bf[0] = __float_as_uint(Vs[jj * VST + dn]);
                bf[1] = __float_as_uint(Vs[(jj + 4) * VST + dn]);
                mma_tf32(o[dt], af, bf);
            }
        }
    }

    float inv0 = 1.0f / l0;
    float inv1 = 1.0f / l1;
    int r0 = i0 + rbase + qr;
    float* ob0 = g_attno + (tokBase + r0) * Dz + h * HDz;
    float* ob1 = g_attno + (tokBase + r0 + 8) * Dz + h * HDz;
    #pragma unroll
    for (int dt = 0; dt < 8; dt++) {
        int d = dt * 8 + 2 * qk;
        *(float2*)(ob0 + d) = make_float2(roundtf(o[dt][0] * inv0),
                                          roundtf(o[dt][1] * inv0));
        *(float2*)(ob1 + d) = make_float2(roundtf(o[dt][2] * inv1),
                                          roundtf(o[dt][3] * inv1));
    }
}

// ---------------------------------------------------------------------------
// Residual + LayerNorm (writes g_h fp32 + g_hr tf32; sel=1: last-layer rows)
// ---------------------------------------------------------------------------
__global__ void residual_ln_kernel(const float* __restrict__ r,
                                   const float* __restrict__ g,
                                   const float* __restrict__ be,
                                   int sel) {
    int idx = blockIdx.x * 2 + (threadIdx.x >> 7);
    int tok;
    if (sel == 0) {
        tok = idx;
    } else {
        int tile = idx >> 7;
        int within = idx & 127;
        tok = tile * 512 + 384 + within;
    }
    int c = (threadIdx.x & 127) << 2;
    size_t off = (size_t)tok * Dz + c;

    float4 hv = *(const float4*)&g_h[off];
    float4 rv = *(const float4*)&r[off];
    float x0 = hv.x + rv.x, x1 = hv.y + rv.y;
    float x2 = hv.z + rv.z, x3 = hv.w + rv.w;

    float s = x0 + x1 + x2 + x3;
    float q = x0 * x0 + x1 * x1 + x2 * x2 + x3 * x3;
    #pragma unroll
    for (int o2 = 16; o2 > 0; o2 >>= 1) {
        s += __shfl_xor_sync(0xffffffffu, s, o2);
        q += __shfl_xor_sync(0xffffffffu, q, o2);
    }

    __shared__ float ws[8][2];
    int w = threadIdx.x >> 5;
    if ((threadIdx.x & 31) == 0) { ws[w][0] = s; ws[w][1] = q; }
    __syncthreads();

    int wb = (threadIdx.x >> 7) << 2;
    s = ws[wb][0] + ws[wb + 1][0] + ws[wb + 2][0] + ws[wb + 3][0];
    q = ws[wb][1] + ws[wb + 1][1] + ws[wb + 2][1] + ws[wb + 3][1];

    float mu = s * (1.0f / Dz);
    float var = q * (1.0f / Dz) - mu * mu;
    float inv = rsqrtf(var + 1e-5f);

    float4 gv = *(const float4*)&g[c];
    float4 bv = *(const float4*)&be[c];
    float4 outv, outr;
    outv.x = (x0 - mu) * inv * gv.x + bv.x;
    outv.y = (x1 - mu) * inv * gv.y + bv.y;
    outv.z = (x2 - mu) * inv * gv.z + bv.z;
    outv.w = (x3 - mu) * inv * gv.w + bv.w;
    outr.x = roundtf(outv.x);
    outr.y = roundtf(outv.y);
    outr.z = roundtf(outv.z);
    outr.w = roundtf(outv.w);
    *(float4*)&g_h[off] = outv;
    *(float4*)&g_hr[off] = outr;
}

// ---------------------------------------------------------------------------
// Head
// ---------------------------------------------------------------------------
__global__ void head_kernel(const float* __restrict__ w_h1,
                            const float* __restrict__ b_h1,
                            const float* __restrict__ w_h2,
                            const float* __restrict__ b_h2,
                            float* __restrict__ out) {
    int b = blockIdx.x;
    int tid = threadIdx.x;
    int t = b * Sz + (Sz - 1);
    __shared__ float hrow[Dz];
    __shared__ float mid[Dz / 2];

    hrow[tid]       = g_h[(size_t)t * Dz + tid];
    hrow[tid + 256] = g_h[(size_t)t * Dz + tid + 256];
    __syncthreads();

    float acc = b_h1[tid];
    #pragma unroll 8
    for (int k = 0; k < Dz; k++) acc += hrow[k] * w_h1[k * (Dz / 2) + tid];
    mid[tid] = gelu_exact(acc);
    __syncthreads();

    if (tid < OUTz) {
        float o = b_h2[tid];
        for (int j = 0; j < Dz / 2; j++) o += mid[j] * w_h2[j * OUTz + tid];
        out[b * OUTz + tid] = o;
    }
}

// ---------------------------------------------------------------------------
// Launch
// ---------------------------------------------------------------------------
extern "C" void kernel_launch(void* const* d_in, const int* in_sizes, int n_in,
                              void* d_out, int out_size) {
    const float* x     = (const float*)d_in[0];
    const float* w_in  = (const float*)d_in[1];
    const float* b_in  = (const float*)d_in[2];
    const float* g_in  = (const float*)d_in[3];
    const float* be_in = (const float*)d_in[4];
    const float* w_qkv = (const float*)d_in[5];
    const float* b_qkv = (const float*)d_in[6];
    const float* w_out = (const float*)d_in[7];
    const float* b_out = (const float*)d_in[8];
    const float* g1    = (const float*)d_in[9];
    const float* be1   = (const float*)d_in[10];
    const float* w_ff1 = (const float*)d_in[11];
    const float* b_ff1 = (const float*)d_in[12];
    const float* w_ff2 = (const float*)d_in[13];
    const float* b_ff2 = (const float*)d_in[14];
    const float* g2    = (const float*)d_in[15];
    const float* be2   = (const float*)d_in[16];
    const float* w_h1  = (const float*)d_in[17];
    const float* b_h1  = (const float*)d_in[18];
    const float* w_h2  = (const float*)d_in[19];
    const float* b_h2  = (const float*)d_in[20];
    float* out = (float*)d_out;

    static float *p_h = nullptr, *p_hr = nullptr, *p_qkv = nullptr,
                 *p_attno = nullptr, *p_ff = nullptr, *p_res = nullptr,
                 *p_wt = nullptr;
    if (!p_h) {
        cudaGetSymbolAddress((void**)&p_h, g_h);
        cudaGetSymbolAddress((void**)&p_hr, g_hr);
        cudaGetSymbolAddress((void**)&p_qkv, g_qkv);
        cudaGetSymbolAddress((void**)&p_attno, g_attno);
        cudaGetSymbolAddress((void**)&p_ff, g_ff);
        cudaGetSymbolAddress((void**)&p_res, g_res);
        cudaGetSymbolAddress((void**)&p_wt, g_wt);
        cudaFuncSetAttribute(attn_flash_tc,
                             cudaFuncAttributeMaxDynamicSharedMemorySize,
                             ATTN_SMEM);
        cudaFuncSetAttribute(sgemm_tc<0>,
                             cudaFuncAttributeMaxDynamicSharedMemorySize,
                             GEMM_SMEM);
        cudaFuncSetAttribute(sgemm_tc<2>,
                             cudaFuncAttributeMaxDynamicSharedMemorySize,
                             GEMM_SMEM);
        cudaFuncSetAttribute(sgemm_tc<3>,
                             cudaFuncAttributeMaxDynamicSharedMemorySize,
                             GEMM_SMEM);
    }

    // Transpose + round all weights into g_wt (Wt[n][k])
    {
        dim3 blk(32, 8);
        transpose_round<<<dim3((3 * Dz) / 32, Dz / 32, Lz), blk>>>(
            w_qkv, p_wt + WT_QKV, Dz, 3 * Dz);
        transpose_round<<<dim3(Dz / 32, Dz / 32, Lz), blk>>>(
            w_out, p_wt + WT_OUT, Dz, Dz);
        transpose_round<<<dim3(FFz / 32, Dz / 32, Lz), blk>>>(
            w_ff1, p_wt + WT_FF1, Dz, FFz);
        transpose_round<<<dim3(Dz / 32, FFz / 32, Lz), blk>>>(
            w_ff2, p_wt + WT_FF2, FFz, Dz);
    }

    embed_kernel<<<BS, 256>>>(x, w_in, b_in, g_in, be_in);

    for (int l = 0; l < Lz; l++) {
        const float* wqkv_l = p_wt + WT_QKV + (size_t)l * Dz * 3 * Dz;
        const float* bqkv_l = b_qkv + (size_t)l * 3 * Dz;
        const float* wout_l = p_wt + WT_OUT + (size_t)l * Dz * Dz;
        const float* bout_l = b_out + (size_t)l * Dz;
        const float* wff1_l = p_wt + WT_FF1 + (size_t)l * Dz * FFz;
        const float* bff1_l = b_ff1 + (size_t)l * FFz;
        const float* wff2_l = p_wt + WT_FF2 + (size_t)l * FFz * Dz;
        const float* bff2_l = b_ff2 + (size_t)l * Dz;
        bool last = (l == Lz - 1);

        if (!last) {
            sgemm_tc<2><<<dim3((3 * Dz) / TBN, BS / TBM), 256, GEMM_SMEM>>>(
                p_hr, wqkv_l, bqkv_l, p_qkv, BS, 3 * Dz, Dz, 1, 0, 0);

            attn_flash_tc<<<dim3(Sz / 64, Bz * Hz), 128, ATTN_SMEM>>>(0);

            sgemm_tc<0><<<dim3(Dz / TBN, BS / TBM), 256, GEMM_SMEM>>>(
                p_attno, wout_l, bout_l, p_res, BS, Dz, Dz, 1, 0, 0);

            residual_ln_kernel<<<BS / 2, 256>>>(p_res, g1 + (size_t)l * Dz,
                                                be1 + (size_t)l * Dz, 0);

            sgemm_tc<3><<<dim3(FFz / TBN, BS / TBM), 256, GEMM_SMEM>>>(
                p_hr, wff1_l, bff1_l, p_ff, BS, FFz, Dz, 1, 0, 0);

            sgemm_tc<0><<<dim3(Dz / TBN, BS / TBM), 256, GEMM_SMEM>>>(
                p_ff, wff2_l, bff2_l, p_res, BS, Dz, FFz, 1, 0, 0);

            residual_ln_kernel<<<BS / 2, 256>>>(p_res, g2 + (size_t)l * Dz,
                                                be2 + (size_t)l * Dz, 0);
        } else {
            sgemm_tc<2><<<dim3((2 * Dz) / TBN, BS / TBM), 256, GEMM_SMEM>>>(
                p_hr, wqkv_l, bqkv_l, p_qkv, BS, 3 * Dz, Dz, 1, 0, Dz);
            sgemm_tc<2><<<dim3(Dz / TBN, Bz), 256, GEMM_SMEM>>>(
                p_hr, wqkv_l, bqkv_l, p_qkv, BS, 3 * Dz, Dz, 4, 3, 0);

            attn_flash_tc<<<dim3(1, Bz * Hz), 128, ATTN_SMEM>>>(7);

            sgemm_tc<0><<<dim3(Dz / TBN, Bz), 256, GEMM_SMEM>>>(
                p_attno, wout_l, bout_l, p_res, BS, Dz, Dz, 4, 3, 0);

            residual_ln_kernel<<<Bz * 64, 256>>>(p_res, g1 + (size_t)l * Dz,
                                                 be1 + (size_t)l * Dz, 1);

            sgemm_tc<3><<<dim3(FFz / TBN, Bz), 256, GEMM_SMEM>>>(
                p_hr, wff1_l, bff1_l, p_ff, BS, FFz, Dz, 4, 3, 0);

            sgemm_tc<0><<<dim3(Dz / TBN, Bz), 256, GEMM_SMEM>>>(
                p_ff, wff2_l, bff2_l, p_res, BS, Dz, FFz, 4, 3, 0);

            residual_ln_kernel<<<Bz * 64, 256>>>(p_res, g2 + (size_t)l * Dz,
                                                 be2 + (size_t)l * Dz, 1);
        }
    }

    head_kernel<<<Bz, 256>>>(w_h1, b_h1, w_h2, b_h2, out);
}

// round 16
// speedup vs baseline: 1.0009x; 1.0009x over previous
#include <cuda_runtime.h>
#include <math.h>
#include <stdint.h>

// ---------------------------------------------------------------------------
// Problem constants
// ---------------------------------------------------------------------------
#define Bz  32
#define Sz  512
#define Dz  512
#define Hz  8
#define HDz 64
#define FFz 2048
#define Lz  6
#define INz 32
#define OUTz 3
#define BS  (Bz * Sz)

// ---------------------------------------------------------------------------
// Scratch buffers
// ---------------------------------------------------------------------------
__device__ float g_h[BS * Dz];           // residual stream (full fp32)
__device__ float g_hr[BS * Dz];          // tf32-rounded copy (GEMM A input)
__device__ float g_qkv[BS * 3 * Dz];     // tf32-rounded by qkv epilogue
__device__ float g_attno[BS * Dz];       // tf32-rounded by attention epilogue
__device__ float g_ff[BS * FFz];         // tf32-rounded by ff1 epilogue
__device__ float g_res[BS * Dz];         // full fp32 (residual branch)

// Transposed + tf32-rounded weights: Wt[n][k]
#define WT_QKV 0
#define WT_OUT (Lz * Dz * 3 * Dz)
#define WT_FF1 (WT_OUT + Lz * Dz * Dz)
#define WT_FF2 (WT_FF1 + Lz * Dz * FFz)
#define WT_TOTAL (WT_FF2 + Lz * FFz * Dz)
__device__ float g_wt[WT_TOTAL];

// ---------------------------------------------------------------------------
// Helpers
// ---------------------------------------------------------------------------
__device__ __forceinline__ float gelu_exact(float x) {
    return 0.5f * x * (1.0f + erff(x * 0.70710678118654752f));
}

__device__ __forceinline__ uint32_t f2tf32(float x) {
    uint32_t u;
    asm("cvt.rna.tf32.f32 %0, %1;" : "=r"(u) : "f"(x));
    return u;
}
__device__ __forceinline__ float roundtf(float x) {
    return __uint_as_float(f2tf32(x));
}

__device__ __forceinline__ void cp_async16(void* smem_dst, const void* gmem_src) {
    uint32_t s = (uint32_t)__cvta_generic_to_shared(smem_dst);
    asm volatile("cp.async.ca.shared.global [%0], [%1], 16;" :: "r"(s), "l"(gmem_src));
}
#define CP_COMMIT()  asm volatile("cp.async.commit_group;")
#define CP_WAIT2()   asm volatile("cp.async.wait_group 2;")
#define CP_WAIT0()   asm volatile("cp.async.wait_group 0;")

__device__ __forceinline__ void mma_tf32(float* c, const uint32_t* a, const uint32_t* b) {
    asm volatile(
        "mma.sync.aligned.m16n8k8.row.col.f32.tf32.tf32.f32 "
        "{%0,%1,%2,%3},{%4,%5,%6,%7},{%8,%9},{%0,%1,%2,%3};"
        : "+f"(c[0]), "+f"(c[1]), "+f"(c[2]), "+f"(c[3])
        : "r"(a[0]), "r"(a[1]), "r"(a[2]), "r"(a[3]), "r"(b[0]), "r"(b[1]));
}

__device__ __forceinline__ void ldsm_x4(uint32_t* r, const float* p) {
    uint32_t a = (uint32_t)__cvta_generic_to_shared(p);
    asm volatile("ldmatrix.sync.aligned.m8n8.x4.shared.b16 {%0,%1,%2,%3}, [%4];"
        : "=r"(r[0]), "=r"(r[1]), "=r"(r[2]), "=r"(r[3]) : "r"(a));
}

__device__ __forceinline__ float block_reduce_sum_256(float v, float* red) {
    int tid = threadIdx.x;
    red[tid] = v;
    __syncthreads();
    #pragma unroll
    for (int s = 128; s > 0; s >>= 1) {
        if (tid < s) red[tid] += red[tid + s];
        __syncthreads();
    }
    float r = red[0];
    __syncthreads();
    return r;
}

// ---------------------------------------------------------------------------
// Weight transpose + tf32 round: dst[l][n][k] = tf32(src[l][k][n])
// ---------------------------------------------------------------------------
__global__ void transpose_round(const float* __restrict__ src,
                                float* __restrict__ dst, int K, int N) {
    __shared__ float t[32][33];
    int l = blockIdx.z;
    src += (size_t)l * K * N;
    dst += (size_t)l * K * N;
    int n0 = blockIdx.x * 32;
    int k0 = blockIdx.y * 32;
    int tx = threadIdx.x, ty = threadIdx.y;
    #pragma unroll
    for (int i = 0; i < 32; i += 8)
        t[ty + i][tx] = src[(size_t)(k0 + ty + i) * N + n0 + tx];
    __syncthreads();
    #pragma unroll
    for (int i = 0; i < 32; i += 8)
        dst[(size_t)(n0 + ty + i) * K + k0 + tx] = roundtf(t[tx][ty + i]);
}

// ---------------------------------------------------------------------------
// Embed (writes g_h fp32 + g_hr tf32)
// ---------------------------------------------------------------------------
__global__ void embed_kernel(const float* __restrict__ x,
                             const float* __restrict__ w_in,
                             const float* __restrict__ b_in,
                             const float* __restrict__ g_in,
                             const float* __restrict__ be_in) {
    int t = blockIdx.x;
    int tid = threadIdx.x;
    __shared__ float xrow[INz];
    __shared__ float vals[Dz];
    __shared__ float red[256];

    if (tid < INz) xrow[tid] = x[t * INz + tid];
    __syncthreads();

    #pragma unroll
    for (int p = 0; p < 2; p++) {
        int c = tid + p * 256;
        float acc = b_in[c];
        #pragma unroll
        for (int k = 0; k < INz; k++) acc += xrow[k] * w_in[k * Dz + c];
        vals[c] = acc;
    }
    __syncthreads();

    float v0 = vals[tid], v1 = vals[tid + 256];
    float mu = block_reduce_sum_256(v0 + v1, red) * (1.0f / Dz);
    float d0 = v0 - mu, d1 = v1 - mu;
    float var = block_reduce_sum_256(d0 * d0 + d1 * d1, red) * (1.0f / Dz);
    float inv = rsqrtf(var + 1e-5f);

    int s = t % Sz;
    float pos = (float)s;
    const float kLog = 9.210340371976184f / (float)Dz;

    #pragma unroll
    for (int p = 0; p < 2; p++) {
        int c = tid + p * 256;
        float d = (p == 0 ? d0 : d1);
        float y = d * inv * g_in[c] + be_in[c];
        y = gelu_exact(y);
        int i2 = c & ~1;
        float div = __expf(-(float)i2 * kLog);
        float ang = pos * div;
        y += (c & 1) ? cosf(ang) : sinf(ang);
        g_h[t * Dz + c] = y;
        g_hr[t * Dz + c] = roundtf(y);
    }
}

// ---------------------------------------------------------------------------
// TF32 GEMM v9 = R13 winner (128 thr, warp 64x64, natural regs) with a
// 4-stage cp.async pipeline (wait_group 2 -> two tiles of latency tolerance).
// TBK=16, 1 sync/k-iter, A/B fragments via ldmatrix.x4, zero cvt in mainloop.
// ACT: bit0 = gelu, bit1 = round output to tf32.
// ---------------------------------------------------------------------------
#define TBM 128
#define TBN 128
#define TBK 16
#define AST 20
#define GSTG 4
#define GEMM_SMEM ((GSTG * 2 * TBM * AST) * 4)   // 81920 B; 2 CTAs/SM (reg-bound)

template <int ACT>
__global__ __launch_bounds__(128)
void sgemm_tc(const float* __restrict__ A,
              const float* __restrict__ Wt,
              const float* __restrict__ bias,
              float* __restrict__ C,
              int M, int N, int K,
              int rowStride, int rowOff, int colOff) {
    extern __shared__ float gsm[];
    float* Asm = gsm;
    float* Bsm = gsm + GSTG * TBM * AST;

    int tid = threadIdx.x;
    int lane = tid & 31;
    int wid = tid >> 5;
    int wm = wid >> 1;
    int wn = wid & 1;
    int qk = lane & 3;
    int qr = lane >> 2;

    int rowBase = (blockIdx.y * rowStride + rowOff) * TBM;
    int colBase = blockIdx.x * TBN + colOff;

    int lr8 = lane & 7;
    int aoff = (lr8 + ((lane >> 3) & 1) * 8) * AST + ((lane >> 4) << 2);
    int bi = lane >> 3;
    int boff = (((bi >> 1) << 3) + lr8) * AST + ((bi & 1) << 2);

    float acc[4][8][4];
    #pragma unroll
    for (int i = 0; i < 4; i++)
        #pragma unroll
        for (int j = 0; j < 8; j++)
            #pragma unroll
            for (int c = 0; c < 4; c++) acc[i][j][c] = 0.f;

    int nk = K / TBK;

    auto stage = [&](int buf, int k0) {
        float* Ab = Asm + buf * TBM * AST;
        float* Bb = Bsm + buf * TBM * AST;
        #pragma unroll
        for (int p = 0; p < 4; p++) {
            int c = tid + p * 128;
            int row = c >> 2;
            int kc = (c & 3) << 2;
            cp_async16(&Ab[row * AST + kc],
                       A + (size_t)(rowBase + row) * K + k0 + kc);
            cp_async16(&Bb[row * AST + kc],
                       Wt + (size_t)(colBase + row) * K + k0 + kc);
        }
    };

    // Prologue: 3 stages in flight
    stage(0, 0);
    CP_COMMIT();
    stage(1, TBK);
    CP_COMMIT();
    stage(2, 2 * TBK);
    CP_COMMIT();

    for (int kt = 0; kt < nk; kt++) {
        CP_WAIT2();              // stage kt complete (kt+1, kt+2 may be in flight)
        __syncthreads();         // buffer (kt+3)%4's old readers (compute kt-1) done
        if (kt + 3 < nk) {
            stage((kt + 3) % GSTG, (kt + 3) * TBK);
            CP_COMMIT();
        } else {
            CP_COMMIT();         // keep group accounting uniform
        }

        const float* Ab = Asm + (kt % GSTG) * TBM * AST;
        const float* Bb = Bsm + (kt % GSTG) * TBM * AST;

        #pragma unroll
        for (int ks = 0; ks < TBK; ks += 8) {
            uint32_t af[4][4], bfr[4][4];
            #pragma unroll
            for (int mt = 0; mt < 4; mt++)
                ldsm_x4(af[mt], Ab + (wm * 64 + mt * 16) * AST + ks + aoff);
            #pragma unroll
            for (int p = 0; p < 4; p++)
                ldsm_x4(bfr[p], Bb + (wn * 64 + p * 16) * AST + ks + boff);

            #pragma unroll
            for (int mt = 0; mt < 4; mt++)
                #pragma unroll
                for (int nt = 0; nt < 8; nt++)
                    mma_tf32(acc[mt][nt], af[mt], &bfr[nt >> 1][(nt & 1) << 1]);
        }
    }

    #pragma unroll
    for (int mt = 0; mt < 4; mt++) {
        int row0 = rowBase + wm * 64 + mt * 16 + qr;
        #pragma unroll
        for (int nt = 0; nt < 8; nt++) {
            int col0 = colBase + wn * 64 + nt * 8 + 2 * qk;
            float bia0 = bias[col0], bia1 = bias[col0 + 1];
            float v0 = acc[mt][nt][0] + bia0;
            float v1 = acc[mt][nt][1] + bia1;
            float v2 = acc[mt][nt][2] + bia0;
            float v3 = acc[mt][nt][3] + bia1;
            if (ACT & 1) {
                v0 = gelu_exact(v0); v1 = gelu_exact(v1);
                v2 = gelu_exact(v2); v3 = gelu_exact(v3);
            }
            if (ACT & 2) {
                v0 = roundtf(v0); v1 = roundtf(v1);
                v2 = roundtf(v2); v3 = roundtf(v3);
            }
            *(float2*)&C[(size_t)row0 * N + col0] = make_float2(v0, v1);
            *(float2*)&C[(size_t)(row0 + 8) * N + col0] = make_float2(v2, v3);
        }
    }
}

// ---------------------------------------------------------------------------
// Tensor-core flash attention (unchanged)
// ---------------------------------------------------------------------------
#define QST 68
#define KST 68
#define VST 72
#define ATTN_SMEM ((64 * QST + 64 * KST + 64 * VST) * 4)

__global__ __launch_bounds__(128, 4)
void attn_flash_tc(int itOff) {
    extern __shared__ float sm[];
    float* Qs = sm;
    float* Ks = sm + 64 * QST;
    float* Vs = sm + 64 * QST + 64 * KST;

    int itile = blockIdx.x + itOff;
    int bh = blockIdx.y;
    int b = bh / Hz;
    int h = bh % Hz;
    int tid = threadIdx.x;
    int lane = tid & 31;
    int wid = tid >> 5;
    int qk = lane & 3;
    int qr = lane >> 2;
    int rbase = wid * 16;
    int i0 = itile * 64;
    size_t tokBase = (size_t)b * Sz;

    {
        const float* qb = g_qkv + (tokBase + i0) * (3 * Dz) + h * HDz;
        #pragma unroll
        for (int it = 0; it < 8; it++) {
            int idx = tid + it * 128;
            int j = idx >> 4;
            int dq = (idx & 15) << 2;
            cp_async16(&Qs[j * QST + dq], qb + (size_t)j * (3 * Dz) + dq);
        }
        CP_COMMIT();
    }

    float m0 = -1e30f, m1 = -1e30f, l0 = 0.f, l1 = 0.f;
    float o[8][4];
    #pragma unroll
    for (int dt = 0; dt < 8; dt++)
        #pragma unroll
        for (int c = 0; c < 4; c++) o[dt][c] = 0.f;

    for (int jt = 0; jt <= itile; jt++) {
        __syncthreads();
        {
            int j0 = jt * 64;
            const float* base0 = g_qkv + (tokBase + j0) * (3 * Dz) + h * HDz;
            #pragma unroll
            for (int it = 0; it < 8; it++) {
                int idx = tid + it * 128;
                int j = idx >> 4;
                int dq = (idx & 15) << 2;
                const float* base = base0 + (size_t)j * (3 * Dz) + dq;
                cp_async16(&Ks[j * KST + dq], base + Dz);
                cp_async16(&Vs[j * VST + dq], base + 2 * Dz);
            }
        }
        CP_COMMIT();
        CP_WAIT0();
        __syncthreads();

        float s[8][4];
        #pragma unroll
        for (int nt = 0; nt < 8; nt++)
            #pragma unroll
            for (int c = 0; c < 4; c++) s[nt][c] = 0.f;

        #pragma unroll
        for (int ks = 0; ks < 8; ks++) {
            int d0 = ks * 8 + qk;
            uint32_t af[4];
            int r0 = rbase + qr;
            af[0] = __float_as_uint(Qs[r0 * QST + d0]);
            af[1] = __float_as_uint(Qs[(r0 + 8) * QST + d0]);
            af[2] = __float_as_uint(Qs[r0 * QST + d0 + 4]);
            af[3] = __float_as_uint(Qs[(r0 + 8) * QST + d0 + 4]);
            #pragma unroll
            for (int nt = 0; nt < 8; nt++) {
                uint32_t bf[2];
                int jrow = nt * 8 + qr;
                bf[0] = __float_as_uint(Ks[jrow * KST + d0]);
                bf[1] = __float_as_uint(Ks[jrow * KST + d0 + 4]);
                mma_tf32(s[nt], af, bf);
            }
        }

        if (jt == itile) {
            int r0 = rbase + qr;
            #pragma unroll
            for (int nt = 0; nt < 8; nt++) {
                int j = nt * 8 + 2 * qk;
                s[nt][0] = (j > r0)         ? -1e30f : s[nt][0] * 0.125f;
                s[nt][1] = (j + 1 > r0)     ? -1e30f : s[nt][1] * 0.125f;
                s[nt][2] = (j > r0 + 8)     ? -1e30f : s[nt][2] * 0.125f;
                s[nt][3] = (j + 1 > r0 + 8) ? -1e30f : s[nt][3] * 0.125f;
            }
        } else {
            #pragma unroll
            for (int nt = 0; nt < 8; nt++) {
                s[nt][0] *= 0.125f; s[nt][1] *= 0.125f;
                s[nt][2] *= 0.125f; s[nt][3] *= 0.125f;
            }
        }

        float mx0 = -1e30f, mx1 = -1e30f;
        #pragma unroll
        for (int nt = 0; nt < 8; nt++) {
            mx0 = fmaxf(mx0, fmaxf(s[nt][0], s[nt][1]));
            mx1 = fmaxf(mx1, fmaxf(s[nt][2], s[nt][3]));
        }
        mx0 = fmaxf(mx0, __shfl_xor_sync(0xffffffffu, mx0, 1));
        mx0 = fmaxf(mx0, __shfl_xor_sync(0xffffffffu, mx0, 2));
        mx1 = fmaxf(mx1, __shfl_xor_sync(0xffffffffu, mx1, 1));
        mx1 = fmaxf(mx1, __shfl_xor_sync(0xffffffffu, mx1, 2));

        float nm0 = fmaxf(m0, mx0);
        float nm1 = fmaxf(m1, mx1);
        float e0 = __expf(m0 - nm0);
        float e1 = __expf(m1 - nm1);

        float rs0 = 0.f, rs1 = 0.f;
        #pragma unroll
        for (int nt = 0; nt < 8; nt++) {
            s[nt][0] = __expf(s[nt][0] - nm0);
            s[nt][1] = __expf(s[nt][1] - nm0);
            s[nt][2] = __expf(s[nt][2] - nm1);
            s[nt][3] = __expf(s[nt][3] - nm1);
            rs0 += s[nt][0] + s[nt][1];
            rs1 += s[nt][2] + s[nt][3];
        }
        rs0 += __shfl_xor_sync(0xffffffffu, rs0, 1);
        rs0 += __shfl_xor_sync(0xffffffffu, rs0, 2);
        rs1 += __shfl_xor_sync(0xffffffffu, rs1, 1);
        rs1 += __shfl_xor_sync(0xffffffffu, rs1, 2);

        l0 = l0 * e0 + rs0;
        l1 = l1 * e1 + rs1;
        m0 = nm0;
        m1 = nm1;
        #pragma unroll
        for (int dt = 0; dt < 8; dt++) {
            o[dt][0] *= e0; o[dt][1] *= e0;
            o[dt][2] *= e1; o[dt][3] *= e1;
        }

        int srcA = (lane & ~3) | (qk >> 1);
        int srcB = srcA + 2;
        bool odd = (qk & 1) != 0;
        #pragma unroll
        for (int nt = 0; nt < 8; nt++) {
            uint32_t p0 = f2tf32(s[nt][0]);
            uint32_t p1 = f2tf32(s[nt][1]);
            uint32_t p2 = f2tf32(s[nt][2]);
            uint32_t p3 = f2tf32(s[nt][3]);
            uint32_t af[4];
            uint32_t x, y;
            x = __shfl_sync(0xffffffffu, p0, srcA);
            y = __shfl_sync(0xffffffffu, p1, srcA);
            af[0] = odd ? y : x;
            x = __shfl_sync(0xffffffffu, p2, srcA);
            y = __shfl_sync(0xffffffffu, p3, srcA);
            af[1] = odd ? y : x;
            x = __shfl_sync(0xffffffffu, p0, srcB);
            y = __shfl_sync(0xffffffffu, p1, srcB);
            af[2] = odd ? y : x;
            x = __shfl_sync(0xffffffffu, p2, srcB);
            y = __shfl_sync(0xffffffffu, p3, srcB);
            af[3] = odd ? y : x;

            int jj = nt * 8 + qk;
            #pragma unroll
            for (int dt = 0; dt < 8; dt++) {
                uint32_t bf[2];
                int dn = dt * 8 + qr;
                bf[0] = __float_as_uint(Vs[jj * VST + dn]);
                bf[1] = __float_as_uint(Vs[(jj + 4) * VST + dn]);
                mma_tf32(o[dt], af, bf);
            }
        }
    }

    float inv0 = 1.0f / l0;
    float inv1 = 1.0f / l1;
    int r0 = i0 + rbase + qr;
    float* ob0 = g_attno + (tokBase + r0) * Dz + h * HDz;
    float* ob1 = g_attno + (tokBase + r0 + 8) * Dz + h * HDz;
    #pragma unroll
    for (int dt = 0; dt < 8; dt++) {
        int d = dt * 8 + 2 * qk;
        *(float2*)(ob0 + d) = make_float2(roundtf(o[dt][0] * inv0),
                                          roundtf(o[dt][1] * inv0));
        *(float2*)(ob1 + d) = make_float2(roundtf(o[dt][2] * inv1),
                                          roundtf(o[dt][3] * inv1));
    }
}

// ---------------------------------------------------------------------------
// Residual + LayerNorm (writes g_h fp32 + g_hr tf32; sel=1: last-layer rows)
// ---------------------------------------------------------------------------
__global__ void residual_ln_kernel(const float* __restrict__ r,
                                   const float* __restrict__ g,
                                   const float* __restrict__ be,
                                   int sel) {
    int idx = blockIdx.x * 2 + (threadIdx.x >> 7);
    int tok;
    if (sel == 0) {
        tok = idx;
    } else {
        int tile = idx >> 7;
        int within = idx & 127;
        tok = tile * 512 + 384 + within;
    }
    int c = (threadIdx.x & 127) << 2;
    size_t off = (size_t)tok * Dz + c;

    float4 hv = *(const float4*)&g_h[off];
    float4 rv = *(const float4*)&r[off];
    float x0 = hv.x + rv.x, x1 = hv.y + rv.y;
    float x2 = hv.z + rv.z, x3 = hv.w + rv.w;

    float s = x0 + x1 + x2 + x3;
    float q = x0 * x0 + x1 * x1 + x2 * x2 + x3 * x3;
    #pragma unroll
    for (int o2 = 16; o2 > 0; o2 >>= 1) {
        s += __shfl_xor_sync(0xffffffffu, s, o2);
        q += __shfl_xor_sync(0xffffffffu, q, o2);
    }

    __shared__ float ws[8][2];
    int w = threadIdx.x >> 5;
    if ((threadIdx.x & 31) == 0) { ws[w][0] = s; ws[w][1] = q; }
    __syncthreads();

    int wb = (threadIdx.x >> 7) << 2;
    s = ws[wb][0] + ws[wb + 1][0] + ws[wb + 2][0] + ws[wb + 3][0];
    q = ws[wb][1] + ws[wb + 1][1] + ws[wb + 2][1] + ws[wb + 3][1];

    float mu = s * (1.0f / Dz);
    float var = q * (1.0f / Dz) - mu * mu;
    float inv = rsqrtf(var + 1e-5f);

    float4 gv = *(const float4*)&g[c];
    float4 bv = *(const float4*)&be[c];
    float4 outv, outr;
    outv.x = (x0 - mu) * inv * gv.x + bv.x;
    outv.y = (x1 - mu) * inv * gv.y + bv.y;
    outv.z = (x2 - mu) * inv * gv.z + bv.z;
    outv.w = (x3 - mu) * inv * gv.w + bv.w;
    outr.x = roundtf(outv.x);
    outr.y = roundtf(outv.y);
    outr.z = roundtf(outv.z);
    outr.w = roundtf(outv.w);
    *(float4*)&g_h[off] = outv;
    *(float4*)&g_hr[off] = outr;
}

// ---------------------------------------------------------------------------
// Head
// ---------------------------------------------------------------------------
__global__ void head_kernel(const float* __restrict__ w_h1,
                            const float* __restrict__ b_h1,
                            const float* __restrict__ w_h2,
                            const float* __restrict__ b_h2,
                            float* __restrict__ out) {
    int b = blockIdx.x;
    int tid = threadIdx.x;
    int t = b * Sz + (Sz - 1);
    __shared__ float hrow[Dz];
    __shared__ float mid[Dz / 2];

    hrow[tid]       = g_h[(size_t)t * Dz + tid];
    hrow[tid + 256] = g_h[(size_t)t * Dz + tid + 256];
    __syncthreads();

    float acc = b_h1[tid];
    #pragma unroll 8
    for (int k = 0; k < Dz; k++) acc += hrow[k] * w_h1[k * (Dz / 2) + tid];
    mid[tid] = gelu_exact(acc);
    __syncthreads();

    if (tid < OUTz) {
        float o = b_h2[tid];
        for (int j = 0; j < Dz / 2; j++) o += mid[j] * w_h2[j * OUTz + tid];
        out[b * OUTz + tid] = o;
    }
}

// ---------------------------------------------------------------------------
// Launch
// ---------------------------------------------------------------------------
extern "C" void kernel_launch(void* const* d_in, const int* in_sizes, int n_in,
                              void* d_out, int out_size) {
    const float* x     = (const float*)d_in[0];
    const float* w_in  = (const float*)d_in[1];
    const float* b_in  = (const float*)d_in[2];
    const float* g_in  = (const float*)d_in[3];
    const float* be_in = (const float*)d_in[4];
    const float* w_qkv = (const float*)d_in[5];
    const float* b_qkv = (const float*)d_in[6];
    const float* w_out = (const float*)d_in[7];
    const float* b_out = (const float*)d_in[8];
    const float* g1    = (const float*)d_in[9];
    const float* be1   = (const float*)d_in[10];
    const float* w_ff1 = (const float*)d_in[11];
    const float* b_ff1 = (const float*)d_in[12];
    const float* w_ff2 = (const float*)d_in[13];
    const float* b_ff2 = (const float*)d_in[14];
    const float* g2    = (const float*)d_in[15];
    const float* be2   = (const float*)d_in[16];
    const float* w_h1  = (const float*)d_in[17];
    const float* b_h1  = (const float*)d_in[18];
    const float* w_h2  = (const float*)d_in[19];
    const float* b_h2  = (const float*)d_in[20];
    float* out = (float*)d_out;

    static float *p_h = nullptr, *p_hr = nullptr, *p_qkv = nullptr,
                 *p_attno = nullptr, *p_ff = nullptr, *p_res = nullptr,
                 *p_wt = nullptr;
    if (!p_h) {
        cudaGetSymbolAddress((void**)&p_h, g_h);
        cudaGetSymbolAddress((void**)&p_hr, g_hr);
        cudaGetSymbolAddress((void**)&p_qkv, g_qkv);
        cudaGetSymbolAddress((void**)&p_attno, g_attno);
        cudaGetSymbolAddress((void**)&p_ff, g_ff);
        cudaGetSymbolAddress((void**)&p_res, g_res);
        cudaGetSymbolAddress((void**)&p_wt, g_wt);
        cudaFuncSetAttribute(attn_flash_tc,
                             cudaFuncAttributeMaxDynamicSharedMemorySize,
                             ATTN_SMEM);
        cudaFuncSetAttribute(sgemm_tc<0>,
                             cudaFuncAttributeMaxDynamicSharedMemorySize,
                             GEMM_SMEM);
        cudaFuncSetAttribute(sgemm_tc<2>,
                             cudaFuncAttributeMaxDynamicSharedMemorySize,
                             GEMM_SMEM);
        cudaFuncSetAttribute(sgemm_tc<3>,
                             cudaFuncAttributeMaxDynamicSharedMemorySize,
                             GEMM_SMEM);
    }

    // Transpose + round all weights into g_wt (Wt[n][k])
    {
        dim3 blk(32, 8);
        transpose_round<<<dim3((3 * Dz) / 32, Dz / 32, Lz), blk>>>(
            w_qkv, p_wt + WT_QKV, Dz, 3 * Dz);
        transpose_round<<<dim3(Dz / 32, Dz / 32, Lz), blk>>>(
            w_out, p_wt + WT_OUT, Dz, Dz);
        transpose_round<<<dim3(FFz / 32, Dz / 32, Lz), blk>>>(
            w_ff1, p_wt + WT_FF1, Dz, FFz);
        transpose_round<<<dim3(Dz / 32, FFz / 32, Lz), blk>>>(
            w_ff2, p_wt + WT_FF2, FFz, Dz);
    }

    embed_kernel<<<BS, 256>>>(x, w_in, b_in, g_in, be_in);

    for (int l = 0; l < Lz; l++) {
        const float* wqkv_l = p_wt + WT_QKV + (size_t)l * Dz * 3 * Dz;
        const float* bqkv_l = b_qkv + (size_t)l * 3 * Dz;
        const float* wout_l = p_wt + WT_OUT + (size_t)l * Dz * Dz;
        const float* bout_l = b_out + (size_t)l * Dz;
        const float* wff1_l = p_wt + WT_FF1 + (size_t)l * Dz * FFz;
        const float* bff1_l = b_ff1 + (size_t)l * FFz;
        const float* wff2_l = p_wt + WT_FF2 + (size_t)l * FFz * Dz;
        const float* bff2_l = b_ff2 + (size_t)l * Dz;
        bool last = (l == Lz - 1);

        if (!last) {
            sgemm_tc<2><<<dim3((3 * Dz) / TBN, BS / TBM), 128, GEMM_SMEM>>>(
                p_hr, wqkv_l, bqkv_l, p_qkv, BS, 3 * Dz, Dz, 1, 0, 0);

            attn_flash_tc<<<dim3(Sz / 64, Bz * Hz), 128, ATTN_SMEM>>>(0);

            sgemm_tc<0><<<dim3(Dz / TBN, BS / TBM), 128, GEMM_SMEM>>>(
                p_attno, wout_l, bout_l, p_res, BS, Dz, Dz, 1, 0, 0);

            residual_ln_kernel<<<BS / 2, 256>>>(p_res, g1 + (size_t)l * Dz,
                                                be1 + (size_t)l * Dz, 0);

            sgemm_tc<3><<<dim3(FFz / TBN, BS / TBM), 128, GEMM_SMEM>>>(
                p_hr, wff1_l, bff1_l, p_ff, BS, FFz, Dz, 1, 0, 0);

            sgemm_tc<0><<<dim3(Dz / TBN, BS / TBM), 128, GEMM_SMEM>>>(
                p_ff, wff2_l, bff2_l, p_res, BS, Dz, FFz, 1, 0, 0);

            residual_ln_kernel<<<BS / 2, 256>>>(p_res, g2 + (size_t)l * Dz,
                                                be2 + (size_t)l * Dz, 0);
        } else {
            sgemm_tc<2><<<dim3((2 * Dz) / TBN, BS / TBM), 128, GEMM_SMEM>>>(
                p_hr, wqkv_l, bqkv_l, p_qkv, BS, 3 * Dz, Dz, 1, 0, Dz);
            sgemm_tc<2><<<dim3(Dz / TBN, Bz), 128, GEMM_SMEM>>>(
                p_hr, wqkv_l, bqkv_l, p_qkv, BS, 3 * Dz, Dz, 4, 3, 0);

            attn_flash_tc<<<dim3(1, Bz * Hz), 128, ATTN_SMEM>>>(7);

            sgemm_tc<0><<<dim3(Dz / TBN, Bz), 128, GEMM_SMEM>>>(
                p_attno, wout_l, bout_l, p_res, BS, Dz, Dz, 4, 3, 0);

            residual_ln_kernel<<<Bz * 64, 256>>>(p_res, g1 + (size_t)l * Dz,
                                                 be1 + (size_t)l * Dz, 1);

            sgemm_tc<3><<<dim3(FFz / TBN, Bz), 128, GEMM_SMEM>>>(
                p_hr, wff1_l, bff1_l, p_ff, BS, FFz, Dz, 4, 3, 0);

            sgemm_tc<0><<<dim3(Dz / TBN, Bz), 128, GEMM_SMEM>>>(
                p_ff, wff2_l, bff2_l, p_res, BS, Dz, FFz, 4, 3, 0);

            residual_ln_kernel<<<Bz * 64, 256>>>(p_res, g2 + (size_t)l * Dz,
                                                 be2 + (size_t)l * Dz, 1);
        }
    }

    head_kernel<<<Bz, 256>>>(w_h1, b_h1, w_h2, b_h2, out);
}

// round 17
// speedup vs baseline: 1.0931x; 1.0922x over previous
#include <cuda_runtime.h>
#include <math.h>
#include <stdint.h>

// ---------------------------------------------------------------------------
// Problem constants
// ---------------------------------------------------------------------------
#define Bz  32
#define Sz  512
#define Dz  512
#define Hz  8
#define HDz 64
#define FFz 2048
#define Lz  6
#define INz 32
#define OUTz 3
#define BS  (Bz * Sz)

// ---------------------------------------------------------------------------
// Scratch buffers
// ---------------------------------------------------------------------------
__device__ float g_h[BS * Dz];           // residual stream (full fp32)
__device__ float g_hr[BS * Dz];          // tf32-rounded copy (GEMM A input)
__device__ float g_qkv[BS * 3 * Dz];     // tf32-rounded by qkv epilogue
__device__ float g_attno[BS * Dz];       // tf32-rounded by attention epilogue
__device__ float g_ff[BS * FFz];         // tf32-rounded by ff1 epilogue
__device__ float g_res[BS * Dz];         // full fp32 (residual branch)

// Transposed + tf32-rounded weights: Wt[n][k]
#define WT_QKV 0
#define WT_OUT (Lz * Dz * 3 * Dz)
#define WT_FF1 (WT_OUT + Lz * Dz * Dz)
#define WT_FF2 (WT_FF1 + Lz * Dz * FFz)
#define WT_TOTAL (WT_FF2 + Lz * FFz * Dz)
__device__ float g_wt[WT_TOTAL];

// ---------------------------------------------------------------------------
// Helpers
// ---------------------------------------------------------------------------
__device__ __forceinline__ float gelu_exact(float x) {
    return 0.5f * x * (1.0f + erff(x * 0.70710678118654752f));
}

__device__ __forceinline__ uint32_t f2tf32(float x) {
    uint32_t u;
    asm("cvt.rna.tf32.f32 %0, %1;" : "=r"(u) : "f"(x));
    return u;
}
__device__ __forceinline__ float roundtf(float x) {
    return __uint_as_float(f2tf32(x));
}

__device__ __forceinline__ void cp_async16(void* smem_dst, const void* gmem_src) {
    uint32_t s = (uint32_t)__cvta_generic_to_shared(smem_dst);
    asm volatile("cp.async.ca.shared.global [%0], [%1], 16;" :: "r"(s), "l"(gmem_src));
}
#define CP_COMMIT()  asm volatile("cp.async.commit_group;")
#define CP_WAIT1()   asm volatile("cp.async.wait_group 1;")
#define CP_WAIT0()   asm volatile("cp.async.wait_group 0;")

__device__ __forceinline__ void mma_tf32(float* c, const uint32_t* a, const uint32_t* b) {
    asm volatile(
        "mma.sync.aligned.m16n8k8.row.col.f32.tf32.tf32.f32 "
        "{%0,%1,%2,%3},{%4,%5,%6,%7},{%8,%9},{%0,%1,%2,%3};"
        : "+f"(c[0]), "+f"(c[1]), "+f"(c[2]), "+f"(c[3])
        : "r"(a[0]), "r"(a[1]), "r"(a[2]), "r"(a[3]), "r"(b[0]), "r"(b[1]));
}

__device__ __forceinline__ void ldsm_x4(uint32_t* r, const float* p) {
    uint32_t a = (uint32_t)__cvta_generic_to_shared(p);
    asm volatile("ldmatrix.sync.aligned.m8n8.x4.shared.b16 {%0,%1,%2,%3}, [%4];"
        : "=r"(r[0]), "=r"(r[1]), "=r"(r[2]), "=r"(r[3]) : "r"(a));
}

__device__ __forceinline__ float block_reduce_sum_256(float v, float* red) {
    int tid = threadIdx.x;
    red[tid] = v;
    __syncthreads();
    #pragma unroll
    for (int s = 128; s > 0; s >>= 1) {
        if (tid < s) red[tid] += red[tid + s];
        __syncthreads();
    }
    float r = red[0];
    __syncthreads();
    return r;
}

// ---------------------------------------------------------------------------
// Weight transpose + tf32 round: dst[l][n][k] = tf32(src[l][k][n])
// ---------------------------------------------------------------------------
__global__ void transpose_round(const float* __restrict__ src,
                                float* __restrict__ dst, int K, int N) {
    __shared__ float t[32][33];
    int l = blockIdx.z;
    src += (size_t)l * K * N;
    dst += (size_t)l * K * N;
    int n0 = blockIdx.x * 32;
    int k0 = blockIdx.y * 32;
    int tx = threadIdx.x, ty = threadIdx.y;
    #pragma unroll
    for (int i = 0; i < 32; i += 8)
        t[ty + i][tx] = src[(size_t)(k0 + ty + i) * N + n0 + tx];
    __syncthreads();
    #pragma unroll
    for (int i = 0; i < 32; i += 8)
        dst[(size_t)(n0 + ty + i) * K + k0 + tx] = roundtf(t[tx][ty + i]);
}

// ---------------------------------------------------------------------------
// Embed (writes g_h fp32 + g_hr tf32)
// ---------------------------------------------------------------------------
__global__ void embed_kernel(const float* __restrict__ x,
                             const float* __restrict__ w_in,
                             const float* __restrict__ b_in,
                             const float* __restrict__ g_in,
                             const float* __restrict__ be_in) {
    int t = blockIdx.x;
    int tid = threadIdx.x;
    __shared__ float xrow[INz];
    __shared__ float vals[Dz];
    __shared__ float red[256];

    if (tid < INz) xrow[tid] = x[t * INz + tid];
    __syncthreads();

    #pragma unroll
    for (int p = 0; p < 2; p++) {
        int c = tid + p * 256;
        float acc = b_in[c];
        #pragma unroll
        for (int k = 0; k < INz; k++) acc += xrow[k] * w_in[k * Dz + c];
        vals[c] = acc;
    }
    __syncthreads();

    float v0 = vals[tid], v1 = vals[tid + 256];
    float mu = block_reduce_sum_256(v0 + v1, red) * (1.0f / Dz);
    float d0 = v0 - mu, d1 = v1 - mu;
    float var = block_reduce_sum_256(d0 * d0 + d1 * d1, red) * (1.0f / Dz);
    float inv = rsqrtf(var + 1e-5f);

    int s = t % Sz;
    float pos = (float)s;
    const float kLog = 9.210340371976184f / (float)Dz;

    #pragma unroll
    for (int p = 0; p < 2; p++) {
        int c = tid + p * 256;
        float d = (p == 0 ? d0 : d1);
        float y = d * inv * g_in[c] + be_in[c];
        y = gelu_exact(y);
        int i2 = c & ~1;
        float div = __expf(-(float)i2 * kLog);
        float ang = pos * div;
        y += (c & 1) ? cosf(ang) : sinf(ang);
        g_h[t * Dz + c] = y;
        g_hr[t * Dz + c] = roundtf(y);
    }
}

// ---------------------------------------------------------------------------
// TF32 GEMM v10 = R13 geometry (128 thr, warp 64x64, TBK=16, GSTG=3) with
// EXPLICIT dual fragment register sets: both ks-steps' LDSM results live
// simultaneously so the 2nd step's loads overlap the 1st step's MMAs.
// __launch_bounds__(128, 2): 256-reg cap, guarantees 2 CTAs/SM, no spills.
// ACT: bit0 = gelu, bit1 = round output to tf32.
// ---------------------------------------------------------------------------
#define TBM 128
#define TBN 128
#define TBK 16
#define AST 20
#define GSTG 3
#define GEMM_SMEM ((GSTG * 2 * TBM * AST) * 4)   // 61440 B

template <int ACT>
__global__ __launch_bounds__(128, 2)
void sgemm_tc(const float* __restrict__ A,
              const float* __restrict__ Wt,
              const float* __restrict__ bias,
              float* __restrict__ C,
              int M, int N, int K,
              int rowStride, int rowOff, int colOff) {
    extern __shared__ float gsm[];
    float* Asm = gsm;
    float* Bsm = gsm + GSTG * TBM * AST;

    int tid = threadIdx.x;
    int lane = tid & 31;
    int wid = tid >> 5;
    int wm = wid >> 1;
    int wn = wid & 1;
    int qk = lane & 3;
    int qr = lane >> 2;

    int rowBase = (blockIdx.y * rowStride + rowOff) * TBM;
    int colBase = blockIdx.x * TBN + colOff;

    int lr8 = lane & 7;
    int aoff = (lr8 + ((lane >> 3) & 1) * 8) * AST + ((lane >> 4) << 2);
    int bi = lane >> 3;
    int boff = (((bi >> 1) << 3) + lr8) * AST + ((bi & 1) << 2);

    float acc[4][8][4];
    #pragma unroll
    for (int i = 0; i < 4; i++)
        #pragma unroll
        for (int j = 0; j < 8; j++)
            #pragma unroll
            for (int c = 0; c < 4; c++) acc[i][j][c] = 0.f;

    int nk = K / TBK;

    auto stage = [&](int buf, int k0) {
        float* Ab = Asm + buf * TBM * AST;
        float* Bb = Bsm + buf * TBM * AST;
        #pragma unroll
        for (int p = 0; p < 4; p++) {
            int c = tid + p * 128;
            int row = c >> 2;
            int kc = (c & 3) << 2;
            cp_async16(&Ab[row * AST + kc],
                       A + (size_t)(rowBase + row) * K + k0 + kc);
            cp_async16(&Bb[row * AST + kc],
                       Wt + (size_t)(colBase + row) * K + k0 + kc);
        }
    };

    stage(0, 0);
    CP_COMMIT();
    stage(1, TBK);
    CP_COMMIT();

    for (int kt = 0; kt < nk; kt++) {
        CP_WAIT1();
        __syncthreads();
        if (kt + 2 < nk) {
            stage((kt + 2) % GSTG, (kt + 2) * TBK);
            CP_COMMIT();
        } else {
            CP_COMMIT();
        }

        const float* Ab = Asm + (kt % GSTG) * TBM * AST;
        const float* Bb = Bsm + (kt % GSTG) * TBM * AST;

        // Explicit dual fragment sets: all 16 LDSM issued before any MMA,
        // so ks=8's loads overlap ks=0's MMA burst.
        uint32_t af0[4][4], bf0[4][4], af1[4][4], bf1[4][4];
        #pragma unroll
        for (int mt = 0; mt < 4; mt++)
            ldsm_x4(af0[mt], Ab + (wm * 64 + mt * 16) * AST + 0 + aoff);
        #pragma unroll
        for (int p = 0; p < 4; p++)
            ldsm_x4(bf0[p], Bb + (wn * 64 + p * 16) * AST + 0 + boff);
        #pragma unroll
        for (int mt = 0; mt < 4; mt++)
            ldsm_x4(af1[mt], Ab + (wm * 64 + mt * 16) * AST + 8 + aoff);
        #pragma unroll
        for (int p = 0; p < 4; p++)
            ldsm_x4(bf1[p], Bb + (wn * 64 + p * 16) * AST + 8 + boff);

        #pragma unroll
        for (int mt = 0; mt < 4; mt++)
            #pragma unroll
            for (int nt = 0; nt < 8; nt++)
                mma_tf32(acc[mt][nt], af0[mt], &bf0[nt >> 1][(nt & 1) << 1]);
        #pragma unroll
        for (int mt = 0; mt < 4; mt++)
            #pragma unroll
            for (int nt = 0; nt < 8; nt++)
                mma_tf32(acc[mt][nt], af1[mt], &bf1[nt >> 1][(nt & 1) << 1]);
    }

    #pragma unroll
    for (int mt = 0; mt < 4; mt++) {
        int row0 = rowBase + wm * 64 + mt * 16 + qr;
        #pragma unroll
        for (int nt = 0; nt < 8; nt++) {
            int col0 = colBase + wn * 64 + nt * 8 + 2 * qk;
            float bia0 = bias[col0], bia1 = bias[col0 + 1];
            float v0 = acc[mt][nt][0] + bia0;
            float v1 = acc[mt][nt][1] + bia1;
            float v2 = acc[mt][nt][2] + bia0;
            float v3 = acc[mt][nt][3] + bia1;
            if (ACT & 1) {
                v0 = gelu_exact(v0); v1 = gelu_exact(v1);
                v2 = gelu_exact(v2); v3 = gelu_exact(v3);
            }
            if (ACT & 2) {
                v0 = roundtf(v0); v1 = roundtf(v1);
                v2 = roundtf(v2); v3 = roundtf(v3);
            }
            *(float2*)&C[(size_t)row0 * N + col0] = make_float2(v0, v1);
            *(float2*)&C[(size_t)(row0 + 8) * N + col0] = make_float2(v2, v3);
        }
    }
}

// ---------------------------------------------------------------------------
// Tensor-core flash attention (unchanged)
// ---------------------------------------------------------------------------
#define QST 68
#define KST 68
#define VST 72
#define ATTN_SMEM ((64 * QST + 64 * KST + 64 * VST) * 4)

__global__ __launch_bounds__(128, 4)
void attn_flash_tc(int itOff) {
    extern __shared__ float sm[];
    float* Qs = sm;
    float* Ks = sm + 64 * QST;
    float* Vs = sm + 64 * QST + 64 * KST;

    int itile = blockIdx.x + itOff;
    int bh = blockIdx.y;
    int b = bh / Hz;
    int h = bh % Hz;
    int tid = threadIdx.x;
    int lane = tid & 31;
    int wid = tid >> 5;
    int qk = lane & 3;
    int qr = lane >> 2;
    int rbase = wid * 16;
    int i0 = itile * 64;
    size_t tokBase = (size_t)b * Sz;

    {
        const float* qb = g_qkv + (tokBase + i0) * (3 * Dz) + h * HDz;
        #pragma unroll
        for (int it = 0; it < 8; it++) {
            int idx = tid + it * 128;
            int j = idx >> 4;
            int dq = (idx & 15) << 2;
            cp_async16(&Qs[j * QST + dq], qb + (size_t)j * (3 * Dz) + dq);
        }
        CP_COMMIT();
    }

    float m0 = -1e30f, m1 = -1e30f, l0 = 0.f, l1 = 0.f;
    float o[8][4];
    #pragma unroll
    for (int dt = 0; dt < 8; dt++)
        #pragma unroll
        for (int c = 0; c < 4; c++) o[dt][c] = 0.f;

    for (int jt = 0; jt <= itile; jt++) {
        __syncthreads();
        {
            int j0 = jt * 64;
            const float* base0 = g_qkv + (tokBase + j0) * (3 * Dz) + h * HDz;
            #pragma unroll
            for (int it = 0; it < 8; it++) {
                int idx = tid + it * 128;
                int j = idx >> 4;
                int dq = (idx & 15) << 2;
                const float* base = base0 + (size_t)j * (3 * Dz) + dq;
                cp_async16(&Ks[j * KST + dq], base + Dz);
                cp_async16(&Vs[j * VST + dq], base + 2 * Dz);
            }
        }
        CP_COMMIT();
        CP_WAIT0();
        __syncthreads();

        float s[8][4];
        #pragma unroll
        for (int nt = 0; nt < 8; nt++)
            #pragma unroll
            for (int c = 0; c < 4; c++) s[nt][c] = 0.f;

        #pragma unroll
        for (int ks = 0; ks < 8; ks++) {
            int d0 = ks * 8 + qk;
            uint32_t af[4];
            int r0 = rbase + qr;
            af[0] = __float_as_uint(Qs[r0 * QST + d0]);
            af[1] = __float_as_uint(Qs[(r0 + 8) * QST + d0]);
            af[2] = __float_as_uint(Qs[r0 * QST + d0 + 4]);
            af[3] = __float_as_uint(Qs[(r0 + 8) * QST + d0 + 4]);
            #pragma unroll
            for (int nt = 0; nt < 8; nt++) {
                uint32_t bf[2];
                int jrow = nt * 8 + qr;
                bf[0] = __float_as_uint(Ks[jrow * KST + d0]);
                bf[1] = __float_as_uint(Ks[jrow * KST + d0 + 4]);
                mma_tf32(s[nt], af, bf);
            }
        }

        if (jt == itile) {
            int r0 = rbase + qr;
            #pragma unroll
            for (int nt = 0; nt < 8; nt++) {
                int j = nt * 8 + 2 * qk;
                s[nt][0] = (j > r0)         ? -1e30f : s[nt][0] * 0.125f;
                s[nt][1] = (j + 1 > r0)     ? -1e30f : s[nt][1] * 0.125f;
                s[nt][2] = (j > r0 + 8)     ? -1e30f : s[nt][2] * 0.125f;
                s[nt][3] = (j + 1 > r0 + 8) ? -1e30f : s[nt][3] * 0.125f;
            }
        } else {
            #pragma unroll
            for (int nt = 0; nt < 8; nt++) {
                s[nt][0] *= 0.125f; s[nt][1] *= 0.125f;
                s[nt][2] *= 0.125f; s[nt][3] *= 0.125f;
            }
        }

        float mx0 = -1e30f, mx1 = -1e30f;
        #pragma unroll
        for (int nt = 0; nt < 8; nt++) {
            mx0 = fmaxf(mx0, fmaxf(s[nt][0], s[nt][1]));
            mx1 = fmaxf(mx1, fmaxf(s[nt][2], s[nt][3]));
        }
        mx0 = fmaxf(mx0, __shfl_xor_sync(0xffffffffu, mx0, 1));
        mx0 = fmaxf(mx0, __shfl_xor_sync(0xffffffffu, mx0, 2));
        mx1 = fmaxf(mx1, __shfl_xor_sync(0xffffffffu, mx1, 1));
        mx1 = fmaxf(mx1, __shfl_xor_sync(0xffffffffu, mx1, 2));

        float nm0 = fmaxf(m0, mx0);
        float nm1 = fmaxf(m1, mx1);
        float e0 = __expf(m0 - nm0);
        float e1 = __expf(m1 - nm1);

        float rs0 = 0.f, rs1 = 0.f;
        #pragma unroll
        for (int nt = 0; nt < 8; nt++) {
            s[nt][0] = __expf(s[nt][0] - nm0);
            s[nt][1] = __expf(s[nt][1] - nm0);
            s[nt][2] = __expf(s[nt][2] - nm1);
            s[nt][3] = __expf(s[nt][3] - nm1);
            rs0 += s[nt][0] + s[nt][1];
            rs1 += s[nt][2] + s[nt][3];
        }
        rs0 += __shfl_xor_sync(0xffffffffu, rs0, 1);
        rs0 += __shfl_xor_sync(0xffffffffu, rs0, 2);
        rs1 += __shfl_xor_sync(0xffffffffu, rs1, 1);
        rs1 += __shfl_xor_sync(0xffffffffu, rs1, 2);

        l0 = l0 * e0 + rs0;
        l1 = l1 * e1 + rs1;
        m0 = nm0;
        m1 = nm1;
        #pragma unroll
        for (int dt = 0; dt < 8; dt++) {
            o[dt][0] *= e0; o[dt][1] *= e0;
            o[dt][2] *= e1; o[dt][3] *= e1;
        }

        int srcA = (lane & ~3) | (qk >> 1);
        int srcB = srcA + 2;
        bool odd = (qk & 1) != 0;
        #pragma unroll
        for (int nt = 0; nt < 8; nt++) {
            uint32_t p0 = f2tf32(s[nt][0]);
            uint32_t p1 = f2tf32(s[nt][1]);
            uint32_t p2 = f2tf32(s[nt][2]);
            uint32_t p3 = f2tf32(s[nt][3]);
            uint32_t af[4];
            uint32_t x, y;
            x = __shfl_sync(0xffffffffu, p0, srcA);
            y = __shfl_sync(0xffffffffu, p1, srcA);
            af[0] = odd ? y : x;
            x = __shfl_sync(0xffffffffu, p2, srcA);
            y = __shfl_sync(0xffffffffu, p3, srcA);
            af[1] = odd ? y : x;
            x = __shfl_sync(0xffffffffu, p0, srcB);
            y = __shfl_sync(0xffffffffu, p1, srcB);
            af[2] = odd ? y : x;
            x = __shfl_sync(0xffffffffu, p2, srcB);
            y = __shfl_sync(0xffffffffu, p3, srcB);
            af[3] = odd ? y : x;

            int jj = nt * 8 + qk;
            #pragma unroll
            for (int dt = 0; dt < 8; dt++) {
                uint32_t bf[2];
                int dn = dt * 8 + qr;
                bf[0] = __float_as_uint(Vs[jj * VST + dn]);
                bf[1] = __float_as_uint(Vs[(jj + 4) * VST + dn]);
                mma_tf32(o[dt], af, bf);
            }
        }
    }

    float inv0 = 1.0f / l0;
    float inv1 = 1.0f / l1;
    int r0 = i0 + rbase + qr;
    float* ob0 = g_attno + (tokBase + r0) * Dz + h * HDz;
    float* ob1 = g_attno + (tokBase + r0 + 8) * Dz + h * HDz;
    #pragma unroll
    for (int dt = 0; dt < 8; dt++) {
        int d = dt * 8 + 2 * qk;
        *(float2*)(ob0 + d) = make_float2(roundtf(o[dt][0] * inv0),
                                          roundtf(o[dt][1] * inv0));
        *(float2*)(ob1 + d) = make_float2(roundtf(o[dt][2] * inv1),
                                          roundtf(o[dt][3] * inv1));
    }
}

// ---------------------------------------------------------------------------
// Residual + LayerNorm (writes g_h fp32 + g_hr tf32; sel=1: last-layer rows)
// ---------------------------------------------------------------------------
__global__ void residual_ln_kernel(const float* __restrict__ r,
                                   const float* __restrict__ g,
                                   const float* __restrict__ be,
                                   int sel) {
    int idx = blockIdx.x * 2 + (threadIdx.x >> 7);
    int tok;
    if (sel == 0) {
        tok = idx;
    } else {
        int tile = idx >> 7;
        int within = idx & 127;
        tok = tile * 512 + 384 + within;
    }
    int c = (threadIdx.x & 127) << 2;
    size_t off = (size_t)tok * Dz + c;

    float4 hv = *(const float4*)&g_h[off];
    float4 rv = *(const float4*)&r[off];
    float x0 = hv.x + rv.x, x1 = hv.y + rv.y;
    float x2 = hv.z + rv.z, x3 = hv.w + rv.w;

    float s = x0 + x1 + x2 + x3;
    float q = x0 * x0 + x1 * x1 + x2 * x2 + x3 * x3;
    #pragma unroll
    for (int o2 = 16; o2 > 0; o2 >>= 1) {
        s += __shfl_xor_sync(0xffffffffu, s, o2);
        q += __shfl_xor_sync(0xffffffffu, q, o2);
    }

    __shared__ float ws[8][2];
    int w = threadIdx.x >> 5;
    if ((threadIdx.x & 31) == 0) { ws[w][0] = s; ws[w][1] = q; }
    __syncthreads();

    int wb = (threadIdx.x >> 7) << 2;
    s = ws[wb][0] + ws[wb + 1][0] + ws[wb + 2][0] + ws[wb + 3][0];
    q = ws[wb][1] + ws[wb + 1][1] + ws[wb + 2][1] + ws[wb + 3][1];

    float mu = s * (1.0f / Dz);
    float var = q * (1.0f / Dz) - mu * mu;
    float inv = rsqrtf(var + 1e-5f);

    float4 gv = *(const float4*)&g[c];
    float4 bv = *(const float4*)&be[c];
    float4 outv, outr;
    outv.x = (x0 - mu) * inv * gv.x + bv.x;
    outv.y = (x1 - mu) * inv * gv.y + bv.y;
    outv.z = (x2 - mu) * inv * gv.z + bv.z;
    outv.w = (x3 - mu) * inv * gv.w + bv.w;
    outr.x = roundtf(outv.x);
    outr.y = roundtf(outv.y);
    outr.z = roundtf(outv.z);
    outr.w = roundtf(outv.w);
    *(float4*)&g_h[off] = outv;
    *(float4*)&g_hr[off] = outr;
}

// ---------------------------------------------------------------------------
// Head
// ---------------------------------------------------------------------------
__global__ void head_kernel(const float* __restrict__ w_h1,
                            const float* __restrict__ b_h1,
                            const float* __restrict__ w_h2,
                            const float* __restrict__ b_h2,
                            float* __restrict__ out) {
    int b = blockIdx.x;
    int tid = threadIdx.x;
    int t = b * Sz + (Sz - 1);
    __shared__ float hrow[Dz];
    __shared__ float mid[Dz / 2];

    hrow[tid]       = g_h[(size_t)t * Dz + tid];
    hrow[tid + 256] = g_h[(size_t)t * Dz + tid + 256];
    __syncthreads();

    float acc = b_h1[tid];
    #pragma unroll 8
    for (int k = 0; k < Dz; k++) acc += hrow[k] * w_h1[k * (Dz / 2) + tid];
    mid[tid] = gelu_exact(acc);
    __syncthreads();

    if (tid < OUTz) {
        float o = b_h2[tid];
        for (int j = 0; j < Dz / 2; j++) o += mid[j] * w_h2[j * OUTz + tid];
        out[b * OUTz + tid] = o;
    }
}

// ---------------------------------------------------------------------------
// Launch
// ---------------------------------------------------------------------------
extern "C" void kernel_launch(void* const* d_in, const int* in_sizes, int n_in,
                              void* d_out, int out_size) {
    const float* x     = (const float*)d_in[0];
    const float* w_in  = (const float*)d_in[1];
    const float* b_in  = (const float*)d_in[2];
    const float* g_in  = (const float*)d_in[3];
    const float* be_in = (const float*)d_in[4];
    const float* w_qkv = (const float*)d_in[5];
    const float* b_qkv = (const float*)d_in[6];
    const float* w_out = (const float*)d_in[7];
    const float* b_out = (const float*)d_in[8];
    const float* g1    = (const float*)d_in[9];
    const float* be1   = (const float*)d_in[10];
    const float* w_ff1 = (const float*)d_in[11];
    const float* b_ff1 = (const float*)d_in[12];
    const float* w_ff2 = (const float*)d_in[13];
    const float* b_ff2 = (const float*)d_in[14];
    const float* g2    = (const float*)d_in[15];
    const float* be2   = (const float*)d_in[16];
    const float* w_h1  = (const float*)d_in[17];
    const float* b_h1  = (const float*)d_in[18];
    const float* w_h2  = (const float*)d_in[19];
    const float* b_h2  = (const float*)d_in[20];
    float* out = (float*)d_out;

    static float *p_h = nullptr, *p_hr = nullptr, *p_qkv = nullptr,
                 *p_attno = nullptr, *p_ff = nullptr, *p_res = nullptr,
                 *p_wt = nullptr;
    if (!p_h) {
        cudaGetSymbolAddress((void**)&p_h, g_h);
        cudaGetSymbolAddress((void**)&p_hr, g_hr);
        cudaGetSymbolAddress((void**)&p_qkv, g_qkv);
        cudaGetSymbolAddress((void**)&p_attno, g_attno);
        cudaGetSymbolAddress((void**)&p_ff, g_ff);
        cudaGetSymbolAddress((void**)&p_res, g_res);
        cudaGetSymbolAddress((void**)&p_wt, g_wt);
        cudaFuncSetAttribute(attn_flash_tc,
                             cudaFuncAttributeMaxDynamicSharedMemorySize,
                             ATTN_SMEM);
        cudaFuncSetAttribute(sgemm_tc<0>,
                             cudaFuncAttributeMaxDynamicSharedMemorySize,
                             GEMM_SMEM);
        cudaFuncSetAttribute(sgemm_tc<2>,
                             cudaFuncAttributeMaxDynamicSharedMemorySize,
                             GEMM_SMEM);
        cudaFuncSetAttribute(sgemm_tc<3>,
                             cudaFuncAttributeMaxDynamicSharedMemorySize,
                             GEMM_SMEM);
    }

    // Transpose + round all weights into g_wt (Wt[n][k])
    {
        dim3 blk(32, 8);
        transpose_round<<<dim3((3 * Dz) / 32, Dz / 32, Lz), blk>>>(
            w_qkv, p_wt + WT_QKV, Dz, 3 * Dz);
        transpose_round<<<dim3(Dz / 32, Dz / 32, Lz), blk>>>(
            w_out, p_wt + WT_OUT, Dz, Dz);
        transpose_round<<<dim3(FFz / 32, Dz / 32, Lz), blk>>>(
            w_ff1, p_wt + WT_FF1, Dz, FFz);
        transpose_round<<<dim3(Dz / 32, FFz / 32, Lz), blk>>>(
            w_ff2, p_wt + WT_FF2, FFz, Dz);
    }

    embed_kernel<<<BS, 256>>>(x, w_in, b_in, g_in, be_in);

    for (int l = 0; l < Lz; l++) {
        const float* wqkv_l = p_wt + WT_QKV + (size_t)l * Dz * 3 * Dz;
        const float* bqkv_l = b_qkv + (size_t)l * 3 * Dz;
        const float* wout_l = p_wt + WT_OUT + (size_t)l * Dz * Dz;
        const float* bout_l = b_out + (size_t)l * Dz;
        const float* wff1_l = p_wt + WT_FF1 + (size_t)l * Dz * FFz;
        const float* bff1_l = b_ff1 + (size_t)l * FFz;
        const float* wff2_l = p_wt + WT_FF2 + (size_t)l * FFz * Dz;
        const float* bff2_l = b_ff2 + (size_t)l * Dz;
        bool last = (l == Lz - 1);

        if (!last) {
            sgemm_tc<2><<<dim3((3 * Dz) / TBN, BS / TBM), 128, GEMM_SMEM>>>(
                p_hr, wqkv_l, bqkv_l, p_qkv, BS, 3 * Dz, Dz, 1, 0, 0);

            attn_flash_tc<<<dim3(Sz / 64, Bz * Hz), 128, ATTN_SMEM>>>(0);

            sgemm_tc<0><<<dim3(Dz / TBN, BS / TBM), 128, GEMM_SMEM>>>(
                p_attno, wout_l, bout_l, p_res, BS, Dz, Dz, 1, 0, 0);

            residual_ln_kernel<<<BS / 2, 256>>>(p_res, g1 + (size_t)l * Dz,
                                                be1 + (size_t)l * Dz, 0);

            sgemm_tc<3><<<dim3(FFz / TBN, BS / TBM), 128, GEMM_SMEM>>>(
                p_hr, wff1_l, bff1_l, p_ff, BS, FFz, Dz, 1, 0, 0);

            sgemm_tc<0><<<dim3(Dz / TBN, BS / TBM), 128, GEMM_SMEM>>>(
                p_ff, wff2_l, bff2_l, p_res, BS, Dz, FFz, 1, 0, 0);

            residual_ln_kernel<<<BS / 2, 256>>>(p_res, g2 + (size_t)l * Dz,
                                                be2 + (size_t)l * Dz, 0);
        } else {
            sgemm_tc<2><<<dim3((2 * Dz) / TBN, BS / TBM), 128, GEMM_SMEM>>>(
                p_hr, wqkv_l, bqkv_l, p_qkv, BS, 3 * Dz, Dz, 1, 0, Dz);
            sgemm_tc<2><<<dim3(Dz / TBN, Bz), 128, GEMM_SMEM>>>(
                p_hr, wqkv_l, bqkv_l, p_qkv, BS, 3 * Dz, Dz, 4, 3, 0);

            attn_flash_tc<<<dim3(1, Bz * Hz), 128, ATTN_SMEM>>>(7);

            sgemm_tc<0><<<dim3(Dz / TBN, Bz), 128, GEMM_SMEM>>>(
                p_attno, wout_l, bout_l, p_res, BS, Dz, Dz, 4, 3, 0);

            residual_ln_kernel<<<Bz * 64, 256>>>(p_res, g1 + (size_t)l * Dz,
                                                 be1 + (size_t)l * Dz, 1);

            sgemm_tc<3><<<dim3(FFz / TBN, Bz), 128, GEMM_SMEM>>>(
                p_hr, wff1_l, bff1_l, p_ff, BS, FFz, Dz, 4, 3, 0);

            sgemm_tc<0><<<dim3(Dz / TBN, Bz), 128, GEMM_SMEM>>>(
                p_ff, wff2_l, bff2_l, p_res, BS, Dz, FFz, 4, 3, 0);

            residual_ln_kernel<<<Bz * 64, 256>>>(p_res, g2 + (size_t)l * Dz,
                                                 be2 + (size_t)l * Dz, 1);
        }
    }

    head_kernel<<<Bz, 256>>>(w_h1, b_h1, w_h2, b_h2, out);
}